// round 2
// baseline (speedup 1.0000x reference)
#include <cuda_runtime.h>
#include <stdint.h>

// ---------------------------------------------------------------------------
// Multires hash-grid encode (instant-NGP style), 2D, 16 levels, F=2.
// Levels 0..5: dense grid (res+1)^2 entries. Levels 6..15: spatial hash into
// prime table of 524309 entries. Bilinear interp of 4 corners.
// ---------------------------------------------------------------------------

#define NUM_LEVELS   16
#define START_HASH   6
#define N_ENTRIES    524309ULL
#define PS1          19349663ULL
#define N_POINTS     524288

// floor(2^64 / 524309) — Barrett magic (m odd => floor((2^64-1)/m) == floor(2^64/m))
#define MAGIC_M      (0xFFFFFFFFFFFFFFFFULL / N_ENTRIES)

__device__ __constant__ int   c_res[NUM_LEVELS]  = {16,32,64,128,256,512,1024,2048,4096,8192,16384,32768,65536,131072,262144,524288};
__device__ __constant__ int   c_off[NUM_LEVELS]  = {0,289,1378,5603,22244,88293,351462,875771,1400080,1924389,2448698,2973007,3497316,4021625,4545934,5070243};

__device__ __forceinline__ int mod_prime(unsigned long long h) {
    unsigned long long q = __umul64hi(h, MAGIC_M);
    unsigned long long r = h - q * N_ENTRIES;
    if (r >= N_ENTRIES) r -= N_ENTRIES;
    return (int)r;
}

__global__ __launch_bounds__(256) void hashgrid_kernel(
    const float* __restrict__ x,      // [N,2]
    const float* __restrict__ data,   // [TABLE_SIZE,2]
    float* __restrict__ out,          // [N,32]
    int n)
{
    int i = blockIdx.x * blockDim.x + threadIdx.x;
    if (i >= n) return;

    const float2 p = reinterpret_cast<const float2*>(x)[i];
    const float2* __restrict__ tab = reinterpret_cast<const float2*>(data);

    float acc[2 * NUM_LEVELS];

    #pragma unroll
    for (int l = 0; l < NUM_LEVELS; ++l) {
        const float scale = (float)c_res[l];
        const float fx = p.x * scale;
        const float fy = p.y * scale;

        // Replicate reference exactly: trunc(fp32), and hi-corner = trunc(fx + 1.0f)
        const long long x0 = (long long)fx;
        const long long y0 = (long long)fy;
        const long long x1 = (long long)(fx + 1.0f);
        const long long y1 = (long long)(fy + 1.0f);

        const float tx = fx - (float)x0;   // exact: fx < 2^23
        const float ty = fy - (float)y0;

        int i00, i01, i10, i11;
        if (l < START_HASH) {
            const int r1 = c_res[l] + 1;
            const int a0 = (int)x0 * r1;
            const int a1 = (int)x1 * r1;
            i00 = a0 + (int)y0;
            i01 = a0 + (int)y1;
            i10 = a1 + (int)y0;
            i11 = a1 + (int)y1;
        } else {
            const unsigned long long hy0 = (unsigned long long)y0 * PS1;
            const unsigned long long hy1 = (unsigned long long)y1 * PS1;
            i00 = mod_prime((unsigned long long)x0 ^ hy0);
            i01 = mod_prime((unsigned long long)x0 ^ hy1);
            i10 = mod_prime((unsigned long long)x1 ^ hy0);
            i11 = mod_prime((unsigned long long)x1 ^ hy1);
        }
        const int off = c_off[l];

        // Issue all 4 gathers back-to-back for MLP
        const float2 v00 = __ldg(&tab[i00 + off]);
        const float2 v01 = __ldg(&tab[i01 + off]);
        const float2 v10 = __ldg(&tab[i10 + off]);
        const float2 v11 = __ldg(&tab[i11 + off]);

        const float wx0 = 1.0f - tx, wx1 = tx;
        const float wy0 = 1.0f - ty, wy1 = ty;
        const float w00 = wx0 * wy0;
        const float w01 = wx0 * wy1;
        const float w10 = wx1 * wy0;
        const float w11 = wx1 * wy1;

        // corner order 00,01,10,11 like the reference einsum
        float f0 = w00 * v00.x;
        f0 = fmaf(w01, v01.x, f0);
        f0 = fmaf(w10, v10.x, f0);
        f0 = fmaf(w11, v11.x, f0);
        float f1 = w00 * v00.y;
        f1 = fmaf(w01, v01.y, f1);
        f1 = fmaf(w10, v10.y, f1);
        f1 = fmaf(w11, v11.y, f1);

        acc[2 * l]     = f0;
        acc[2 * l + 1] = f1;
    }

    // 8 x STG.128 — each thread writes its full 128B row
    float4* o = reinterpret_cast<float4*>(out + (size_t)i * 32);
    #pragma unroll
    for (int j = 0; j < 8; ++j) {
        o[j] = make_float4(acc[4*j], acc[4*j+1], acc[4*j+2], acc[4*j+3]);
    }
}

extern "C" void kernel_launch(void* const* d_in, const int* in_sizes, int n_in,
                              void* d_out, int out_size) {
    const float* x    = (const float*)d_in[0];   // [N,2] fp32
    const float* data = (const float*)d_in[1];   // [TABLE_SIZE,2] fp32
    float* out        = (float*)d_out;           // [N,32] fp32

    const int n = in_sizes[0] / 2;               // number of points
    const int threads = 256;
    const int blocks  = (n + threads - 1) / threads;
    hashgrid_kernel<<<blocks, threads>>>(x, data, out, n);
}